// round 10
// baseline (speedup 1.0000x reference)
#include <cuda_runtime.h>
#include <cuda_bf16.h>
#include <cstdint>

// ---------------------------------------------------------------------------
// GraphConv stack, R8: linearity restructure. Since scatter-add is linear,
//   agg(X@W1^T + b1) = (agg X)@W1^T + deg*b1.
// Per layer: [agg: Xagg = gather-sum of X]  then
//   Y = relu( X@W0^T + Xagg@W1^T + b0 + deg*b1 )   (single fused HMMA GEMM,
// one output, relu in epilogue; activations stored pre-relu'd).
// HMMA bf16 3-term split (hi/lo) keeps fp32-grade precision.
// ---------------------------------------------------------------------------

#define D 128
#define MAXN 100352
#define MAXE 310016
#define MAXL 16

typedef unsigned int uint32;

// Scratch (device globals: no allocation allowed)
__device__ __align__(128) float g_y1[(size_t)MAXN * D];   // relu'd layer-1 out
__device__ __align__(128) float g_ya[(size_t)MAXN * D];   // ping
__device__ __align__(128) float g_yb[(size_t)MAXN * D];   // pong
__device__ __align__(128) float g_n [(size_t)MAXN * D];   // Xagg
__device__ __align__(128) __nv_bfloat16 g_wimg[(size_t)MAXL * 4 * D * D];
// CSR scratch
__device__ int g_deg[MAXN];
__device__ int g_rowstart[MAXN];
__device__ int g_wr[MAXN];
__device__ int g_adj[2 * MAXE];
__device__ int g_cursor;

// ---------------- helpers ---------------------------------------------------
__device__ __forceinline__ uint32 smem_to_u32(const void* p) {
    uint32 a;
    asm("{ .reg .u64 t; cvta.to.shared.u64 t, %1; cvt.u32.u64 %0, t; }"
        : "=r"(a) : "l"(p));
    return a;
}
__device__ __forceinline__ void ldm_x4(uint32 a, uint32* r) {
    asm volatile("ldmatrix.sync.aligned.m8n8.x4.shared.b16 {%0,%1,%2,%3}, [%4];"
                 : "=r"(r[0]), "=r"(r[1]), "=r"(r[2]), "=r"(r[3]) : "r"(a));
}
__device__ __forceinline__ void mma_bf16(float* d, const uint32* a, const uint32* b) {
    asm volatile(
        "mma.sync.aligned.m16n8k16.row.col.f32.bf16.bf16.f32 "
        "{%0,%1,%2,%3}, {%4,%5,%6,%7}, {%8,%9}, {%0,%1,%2,%3};"
        : "+f"(d[0]), "+f"(d[1]), "+f"(d[2]), "+f"(d[3])
        : "r"(a[0]), "r"(a[1]), "r"(a[2]), "r"(a[3]), "r"(b[0]), "r"(b[1]));
}
#define CP_ASYNC16(dst, src) \
    asm volatile("cp.async.cg.shared.global [%0], [%1], 16;" \
                 :: "r"(dst), "l"(src) : "memory")
#define CP_COMMIT() asm volatile("cp.async.commit_group;" ::: "memory")
#define CP_WAIT0()  asm volatile("cp.async.wait_group 0;" ::: "memory")

// Swizzled layout for a [rows x 128] bf16 k-major tile:
// row r, 16B chunk c (0..15): off = r*256 + ((c ^ (r&7)) << 4)
__host__ __device__ __forceinline__ uint32 tile_off(int r, int c) {
    return (uint32)(r * 256 + (((c) ^ (r & 7)) << 4));
}

// SMEM: A double buffer 2 x 32KB {Xhi 8K, Xlo 8K, Ghi 8K, Glo 8K} | B 128KB
#define SM_ABUF  32768
#define A_XLO    8192
#define A_GHI    16384
#define A_GLO    24576
#define SM_B     65536
#define SM_TOTAL (65536 + 131072)   // 192 KB

// ---------------------------------------------------------------------------
// Weight prep: split fp32 W into bf16 hi/lo in the swizzled image layout.
// Image layout per layer: {W0hi, W0lo, W1hi, W1lo}, 32KB each.
// ---------------------------------------------------------------------------
__global__ __launch_bounds__(256) void convert_weights(
    const float* __restrict__ W0_1, const float* __restrict__ W1_1,
    const float* __restrict__ W0_h, const float* __restrict__ W1_h,
    __nv_bfloat16* __restrict__ wimg)
{
    int m = blockIdx.x;
    int layer = m >> 1, sel = m & 1;
    const float* src;
    if (layer == 0) src = sel ? W1_1 : W0_1;
    else            src = (sel ? W1_h : W0_h) + (size_t)(layer - 1) * D * D;
    char* hi = (char*)(wimg + ((size_t)layer * 4 + sel * 2) * (D * D));
    char* lo = hi + D * D * 2;

    for (int e = threadIdx.x; e < 2048; e += blockDim.x) {   // 16B chunks
        int r = e >> 4, c = e & 15;
        const float* s = src + r * D + c * 8;
        uint32 h[4], l[4];
#pragma unroll
        for (int q = 0; q < 4; q++) {
            float x0 = s[q * 2], x1 = s[q * 2 + 1];
            __nv_bfloat16 h0 = __float2bfloat16(x0), h1 = __float2bfloat16(x1);
            __nv_bfloat16 l0 = __float2bfloat16(x0 - __bfloat162float(h0));
            __nv_bfloat16 l1 = __float2bfloat16(x1 - __bfloat162float(h1));
            __nv_bfloat162 hp = __halves2bfloat162(h0, h1);
            __nv_bfloat162 lp = __halves2bfloat162(l0, l1);
            h[q] = *(uint32*)&hp;
            l[q] = *(uint32*)&lp;
        }
        uint32 off = tile_off(r, c);
        *(uint4*)(hi + off) = make_uint4(h[0], h[1], h[2], h[3]);
        *(uint4*)(lo + off) = make_uint4(l[0], l[1], l[2], l[3]);
    }
}

// ---- A tile: 32 rows x 32 float4 x 2 sources = 2048 chunks / 256 thr = 8 ---
__device__ __forceinline__ void ldA(const float* __restrict__ X,
                                    const float* __restrict__ G, int row0,
                                    int nrows, int tid, float4* pf) {
#pragma unroll
    for (int q = 0; q < 8; q++) {
        int idx = tid + (q & 3) * 256;       // 0..1023
        int r = idx >> 5, cq = idx & 31;
        int gr = row0 + r;
        const float* src = (q < 4) ? X : G;
        float4 v = make_float4(0.f, 0.f, 0.f, 0.f);
        if (gr < nrows) v = __ldg((const float4*)(src + (size_t)gr * D + cq * 4));
        pf[q] = v;
    }
}
__device__ __forceinline__ void cvt1(float x, float y,
                                     uint32& h, uint32& l) {
    __nv_bfloat16 hx = __float2bfloat16(x), hy = __float2bfloat16(y);
    __nv_bfloat16 lx = __float2bfloat16(x - __bfloat162float(hx));
    __nv_bfloat16 ly = __float2bfloat16(y - __bfloat162float(hy));
    __nv_bfloat162 hp = __halves2bfloat162(hx, hy);
    __nv_bfloat162 lp = __halves2bfloat162(lx, ly);
    h = *(uint32*)&hp; l = *(uint32*)&lp;
}
__device__ __forceinline__ void cvtA(char* smem, uint32 bufoff, int tid,
                                     const float4* pf) {
#pragma unroll
    for (int q = 0; q < 8; q++) {
        int idx = tid + (q & 3) * 256;
        int r = idx >> 5, cq = idx & 31;
        uint32 hiOff = bufoff + ((q < 4) ? 0u : (uint32)A_GHI);
        float4 v = pf[q];
        uint32 h0, l0, h1, l1;
        cvt1(v.x, v.y, h0, l0);
        cvt1(v.z, v.w, h1, l1);
        uint32 off = tile_off(r, cq >> 1) + (cq & 1) * 8;
        *(uint2*)(smem + hiOff + off)        = make_uint2(h0, h1);
        *(uint2*)(smem + hiOff + 8192 + off) = make_uint2(l0, l1);
    }
}

// ---------------------------------------------------------------------------
// Persistent fused HMMA GEMM:
//   Y = relu( X@W0^T + G@W1^T + b0 + deg*b1 )        (RELU template: last
// layer variant also just relu — all stored activations are post-relu)
// grid = min(#SM, ntiles). 256 threads = 8 warps; tile 32 rows x 128 cols;
// each warp owns 16 output cols (2 n8 blocks) and all 32 rows (2 m16 blocks).
// ---------------------------------------------------------------------------
__global__ __launch_bounds__(256) void gemm_fused(
    const float* __restrict__ X, const float* __restrict__ G,
    const __nv_bfloat16* __restrict__ wimg,
    const float* __restrict__ b0, const float* __restrict__ b1,
    const int* __restrict__ deg,
    float* __restrict__ Y, int nrows)
{
    extern __shared__ char smem[];
    const uint32 sb = smem_to_u32(smem);
    const int tid  = threadIdx.x;
    const int wid  = tid >> 5;
    const int lane = tid & 31;
    const int ntiles = (nrows + 31) >> 5;

    // ---- B: one 128KB cp.async of the pre-swizzled weight image -----------
    {
        const char* src = (const char*)wimg;
#pragma unroll
        for (int i = 0; i < 32; i++) {
            uint32 off = (uint32)(tid + i * 256) * 16;
            CP_ASYNC16(sb + SM_B + off, src + off);
        }
        CP_COMMIT();
    }

    // ---- prologue: first tile into buffer 0 --------------------------------
    if (blockIdx.x < ntiles) {
        float4 pf[8];
        ldA(X, G, blockIdx.x * 32, nrows, tid, pf);
        cvtA(smem, 0, tid, pf);
    }
    CP_WAIT0();
    __syncthreads();

    // ---- fragment addressing ------------------------------------------------
    const int g  = lane >> 3;
    const int r8 = lane & 7;

    const int rowA = ((g & 1) << 3) + r8;        // swz = r8
    uint32 aRel[2];
#pragma unroll
    for (int i = 0; i < 2; i++) aRel[i] = (uint32)(rowA + i * 16) * 256;

    const int rowB = wid * 16 + ((g >> 1) << 3) + r8;   // swz = r8
    const uint32 bBase = sb + SM_B + (uint32)rowB * 256;

    // bias registers (per thread: 2 j-blocks x (b0,b1) x (x,y))
    float b0x[2], b0y[2], b1x[2], b1y[2];
#pragma unroll
    for (int j = 0; j < 2; j++) {
        int nc = wid * 16 + j * 8 + (lane & 3) * 2;
        b0x[j] = __ldg(b0 + nc); b0y[j] = __ldg(b0 + nc + 1);
        b1x[j] = __ldg(b1 + nc); b1y[j] = __ldg(b1 + nc + 1);
    }

    // ---- main pipelined loop -------------------------------------------------
    int buf = 0;
    for (int t = blockIdx.x; t < ntiles; t += gridDim.x) {
        const int tn = t + gridDim.x;
        const bool have = tn < ntiles;
        float4 pf[8];
        if (have) ldA(X, G, tn * 32, nrows, tid, pf);   // LDG overlaps MMA

        const uint32 abase = sb + (uint32)buf * SM_ABUF;
        const int row0 = t * 32;

        float acc[2][2][4];
#pragma unroll
        for (int i = 0; i < 2; i++)
#pragma unroll
            for (int j = 0; j < 2; j++)
#pragma unroll
                for (int q = 0; q < 4; q++) acc[i][j][q] = 0.f;

#pragma unroll
        for (int k = 0; k < 8; k++) {
            const uint32 offA = (uint32)(((2 * k + (g >> 1)) ^ r8) << 4);
            const uint32 offB = (uint32)(((2 * k + (g & 1)) ^ r8) << 4);

            uint32 xh[2][4], xl[2][4], gh[2][4], gl[2][4];
#pragma unroll
            for (int i = 0; i < 2; i++) {
                ldm_x4(abase + aRel[i] + offA,          xh[i]);
                ldm_x4(abase + aRel[i] + offA + A_XLO,  xl[i]);
                ldm_x4(abase + aRel[i] + offA + A_GHI,  gh[i]);
                ldm_x4(abase + aRel[i] + offA + A_GLO,  gl[i]);
            }
            uint32 w0h[4], w0l[4], w1h[4], w1l[4];
            ldm_x4(bBase + offB,          w0h);
            ldm_x4(bBase + offB + 32768,  w0l);
            ldm_x4(bBase + offB + 65536,  w1h);
            ldm_x4(bBase + offB + 98304,  w1l);

#pragma unroll
            for (int i = 0; i < 2; i++) {
#pragma unroll
                for (int j = 0; j < 2; j++) {
                    float* a = acc[i][j];
                    mma_bf16(a, xh[i], &w0h[j * 2]);   // Xhi*W0hi
                    mma_bf16(a, xh[i], &w0l[j * 2]);   // Xhi*W0lo
                    mma_bf16(a, xl[i], &w0h[j * 2]);   // Xlo*W0hi
                    mma_bf16(a, gh[i], &w1h[j * 2]);   // Ghi*W1hi
                    mma_bf16(a, gh[i], &w1l[j * 2]);   // Ghi*W1lo
                    mma_bf16(a, gl[i], &w1h[j * 2]);   // Glo*W1hi
                }
            }
        }

        // epilogue: + b0 + deg*b1, relu, store
#pragma unroll
        for (int i = 0; i < 2; i++) {
            int r1 = row0 + i * 16 + (lane >> 2);
            int r2 = r1 + 8;
            float d1 = (r1 < nrows) ? (float)__ldg(&deg[r1]) : 0.f;
            float d2 = (r2 < nrows) ? (float)__ldg(&deg[r2]) : 0.f;
#pragma unroll
            for (int j = 0; j < 2; j++) {
                int nc = wid * 16 + j * 8 + (lane & 3) * 2;
                if (r1 < nrows) {
                    float vx = fmaxf(acc[i][j][0] + b0x[j] + d1 * b1x[j], 0.f);
                    float vy = fmaxf(acc[i][j][1] + b0y[j] + d1 * b1y[j], 0.f);
                    *(float2*)(Y + (size_t)r1 * D + nc) = make_float2(vx, vy);
                }
                if (r2 < nrows) {
                    float vx = fmaxf(acc[i][j][2] + b0x[j] + d2 * b1x[j], 0.f);
                    float vy = fmaxf(acc[i][j][3] + b0y[j] + d2 * b1y[j], 0.f);
                    *(float2*)(Y + (size_t)r2 * D + nc) = make_float2(vx, vy);
                }
            }
        }

        if (have) cvtA(smem, (uint32)(buf ^ 1) * SM_ABUF, tid, pf);
        __syncthreads();
        buf ^= 1;
    }
}

// ---------------------------------------------------------------------------
// CSR build (once per call).
// ---------------------------------------------------------------------------
__global__ __launch_bounds__(256) void csr_zero(int* deg, int* cursor, int Nn) {
    int i = blockIdx.x * blockDim.x + threadIdx.x;
    if (i < Nn) deg[i] = 0;
    if (i == 0) *cursor = 0;
}
__global__ __launch_bounds__(256) void csr_count(const int2* __restrict__ edges,
                                                 int* deg, int E) {
    int e = blockIdx.x * blockDim.x + threadIdx.x;
    if (e >= E) return;
    int2 ij = __ldg(&edges[e]);
    atomicAdd(&deg[ij.x], 1);
    atomicAdd(&deg[ij.y], 1);
}
__global__ __launch_bounds__(256) void csr_offsets(const int* __restrict__ deg,
                                                   int* rowstart, int* wr,
                                                   int* cursor, int Nn) {
    int i = blockIdx.x * blockDim.x + threadIdx.x;
    if (i >= Nn) return;
    int s = atomicAdd(cursor, deg[i]);
    rowstart[i] = s;
    wr[i] = s;
}
__global__ __launch_bounds__(256) void csr_fill(const int2* __restrict__ edges,
                                                int* wr, int* adj, int E) {
    int e = blockIdx.x * blockDim.x + threadIdx.x;
    if (e >= E) return;
    int2 ij = __ldg(&edges[e]);
    adj[atomicAdd(&wr[ij.x], 1)] = ij.y;
    adj[atomicAdd(&wr[ij.y], 1)] = ij.x;
}

// ---------------------------------------------------------------------------
// Aggregation: one warp per node. Xagg[node] = sum_{nbr} X[nbr]. Fresh write.
// ---------------------------------------------------------------------------
__global__ __launch_bounds__(256) void agg(
    const int* __restrict__ rowstart, const int* __restrict__ deg,
    const int* __restrict__ adj, const float* __restrict__ X,
    float* __restrict__ Xagg, int Nn)
{
    int gidx = blockIdx.x * blockDim.x + threadIdx.x;
    int node = gidx >> 5;
    int lane = gidx & 31;
    if (node >= Nn) return;
    int d = __ldg(&deg[node]);
    int base = __ldg(&rowstart[node]);

    float4 acc = make_float4(0.f, 0.f, 0.f, 0.f);
    int t = 0;
    for (; t + 2 <= d; t += 2) {
        int n0 = __ldg(&adj[base + t]);
        int n1 = __ldg(&adj[base + t + 1]);
        float4 v0 = __ldg((const float4*)(X + (size_t)n0 * D + lane * 4));
        float4 v1 = __ldg((const float4*)(X + (size_t)n1 * D + lane * 4));
        acc.x += v0.x + v1.x; acc.y += v0.y + v1.y;
        acc.z += v0.z + v1.z; acc.w += v0.w + v1.w;
    }
    if (t < d) {
        int n0 = __ldg(&adj[base + t]);
        float4 v0 = __ldg((const float4*)(X + (size_t)n0 * D + lane * 4));
        acc.x += v0.x; acc.y += v0.y; acc.z += v0.z; acc.w += v0.w;
    }
    *(float4*)(Xagg + (size_t)node * D + lane * 4) = acc;
}

// ---------------------------------------------------------------------------
// z = y1 + ylast (both already relu'd)
// ---------------------------------------------------------------------------
__global__ __launch_bounds__(256) void add_z(
    const float* __restrict__ y1, const float* __restrict__ yl,
    float* __restrict__ z, int nquads)
{
    int idx = blockIdx.x * blockDim.x + threadIdx.x;
    if (idx >= nquads) return;
    float4 a = ((const float4*)y1)[idx];
    float4 b = ((const float4*)yl)[idx];
    a.x += b.x; a.y += b.y; a.z += b.z; a.w += b.w;
    ((float4*)z)[idx] = a;
}

// ---------------------------------------------------------------------------
// Final layer (128 -> 3): vert = z@W0^T + b0 + zagg@W1^T + deg*b1.
// One thread per node.
// ---------------------------------------------------------------------------
__global__ __launch_bounds__(256) void final3(
    const float* __restrict__ z, const float* __restrict__ zagg,
    const float* __restrict__ W0, const float* __restrict__ b0,
    const float* __restrict__ W1, const float* __restrict__ b1,
    const int* __restrict__ deg,
    float* __restrict__ vert, int nrows)
{
    __shared__ float sW0[3 * D], sW1[3 * D], sb0[3], sb1[3];
    for (int t = threadIdx.x; t < 3 * D; t += blockDim.x) {
        sW0[t] = W0[t];
        sW1[t] = W1[t];
    }
    if (threadIdx.x < 3) {
        sb0[threadIdx.x] = b0[threadIdx.x];
        sb1[threadIdx.x] = b1[threadIdx.x];
    }
    __syncthreads();

    int node = blockIdx.x * blockDim.x + threadIdx.x;
    if (node >= nrows) return;

    const float4* z4 = (const float4*)(z    + (size_t)node * D);
    const float4* a4 = (const float4*)(zagg + (size_t)node * D);
    float dg = (float)__ldg(&deg[node]);

    float acc[3];
#pragma unroll
    for (int o = 0; o < 3; o++) acc[o] = sb0[o] + dg * sb1[o];

#pragma unroll 8
    for (int q = 0; q < D / 4; q++) {
        float4 zv = z4[q], av = a4[q];
        int k = q * 4;
#pragma unroll
        for (int o = 0; o < 3; o++) {
            acc[o] = fmaf(zv.x, sW0[o * D + k + 0], acc[o]);
            acc[o] = fmaf(zv.y, sW0[o * D + k + 1], acc[o]);
            acc[o] = fmaf(zv.z, sW0[o * D + k + 2], acc[o]);
            acc[o] = fmaf(zv.w, sW0[o * D + k + 3], acc[o]);
            acc[o] = fmaf(av.x, sW1[o * D + k + 0], acc[o]);
            acc[o] = fmaf(av.y, sW1[o * D + k + 1], acc[o]);
            acc[o] = fmaf(av.z, sW1[o * D + k + 2], acc[o]);
            acc[o] = fmaf(av.w, sW1[o * D + k + 3], acc[o]);
        }
    }
#pragma unroll
    for (int o = 0; o < 3; o++)
        vert[(size_t)node * 3 + o] = acc[o];
}

// ---------------------------------------------------------------------------
extern "C" void kernel_launch(void* const* d_in, const int* in_sizes, int n_in,
                              void* d_out, int out_size)
{
    const float* features = (const float*)d_in[0];
    const int2*  edges    = (const int2*) d_in[1];
    const float* W0_1 = (const float*)d_in[2];
    const float* b0_1 = (const float*)d_in[3];
    const float* W1_1 = (const float*)d_in[4];
    const float* b1_1 = (const float*)d_in[5];
    const float* W0_h = (const float*)d_in[6];
    const float* b0_h = (const float*)d_in[7];
    const float* W1_h = (const float*)d_in[8];
    const float* b1_h = (const float*)d_in[9];
    const float* W0_l = (const float*)d_in[10];
    const float* b0_l = (const float*)d_in[11];
    const float* W1_l = (const float*)d_in[12];
    const float* b1_l = (const float*)d_in[13];

    const int Nn = in_sizes[0] / D;
    const int E  = in_sizes[1] / 2;
    const int Lh = in_sizes[6] / (D * D);

    float* out  = (float*)d_out;
    float* vert = out;                       // [N, 3]
    float* aux  = out + (size_t)Nn * 3;      // [N, 128] = relu'd last hidden

    float *p_y1, *p_ya, *p_yb, *p_n;
    __nv_bfloat16* p_wimg;
    int *p_deg, *p_rs, *p_wr, *p_adj, *p_cur;
    cudaGetSymbolAddress((void**)&p_y1,   g_y1);
    cudaGetSymbolAddress((void**)&p_ya,   g_ya);
    cudaGetSymbolAddress((void**)&p_yb,   g_yb);
    cudaGetSymbolAddress((void**)&p_n,    g_n);
    cudaGetSymbolAddress((void**)&p_wimg, g_wimg);
    cudaGetSymbolAddress((void**)&p_deg,  g_deg);
    cudaGetSymbolAddress((void**)&p_rs,   g_rowstart);
    cudaGetSymbolAddress((void**)&p_wr,   g_wr);
    cudaGetSymbolAddress((void**)&p_adj,  g_adj);
    cudaGetSymbolAddress((void**)&p_cur,  g_cursor);

    cudaFuncSetAttribute(gemm_fused, cudaFuncAttributeMaxDynamicSharedMemorySize, SM_TOTAL);

    int smc = 0;
    if (cudaDeviceGetAttribute(&smc, cudaDevAttrMultiProcessorCount, 0) != cudaSuccess
        || smc <= 0)
        smc = 148;

    const int ntiles      = (Nn + 31) / 32;
    const int gemm_grid   = smc < ntiles ? smc : ntiles;
    const int nquads      = Nn * D / 4;
    const int q_blocks    = (nquads + 255) / 256;
    const int node_blocks = (Nn + 255) / 256;
    const int edge_blocks = (E + 255) / 256;
    const int agg_blocks  = (Nn * 32 + 255) / 256;

    // ---- weight images + CSR build -----------------------------------------
    convert_weights<<<2 * (Lh + 1), 256>>>(W0_1, W1_1, W0_h, W1_h, p_wimg);
    csr_zero<<<node_blocks, 256>>>(p_deg, p_cur, Nn);
    csr_count<<<edge_blocks, 256>>>(edges, p_deg, E);
    csr_offsets<<<node_blocks, 256>>>(p_deg, p_rs, p_wr, p_cur, Nn);
    csr_fill<<<edge_blocks, 256>>>(edges, p_wr, p_adj, E);

    // ---- Layer 1: agg(features), fused GEMM -> relu'd y1 -------------------
    agg<<<agg_blocks, 256>>>(p_rs, p_deg, p_adj, features, p_n, Nn);
    gemm_fused<<<gemm_grid, 256, SM_TOTAL>>>(
        features, p_n, p_wimg, b0_1, b1_1, p_deg, p_y1, Nn);

    // ---- hidden layers (last one writes straight into aux) -----------------
    const float* src = p_y1;
    for (int l = 0; l < Lh; l++) {
        const __nv_bfloat16* wl = p_wimg + (size_t)(l + 1) * 4 * D * D;
        const float* b0 = b0_h + (size_t)l * D;
        const float* b1 = b1_h + (size_t)l * D;
        float* dst = (l == Lh - 1) ? aux : ((l & 1) ? p_yb : p_ya);
        agg<<<agg_blocks, 256>>>(p_rs, p_deg, p_adj, src, p_n, Nn);
        gemm_fused<<<gemm_grid, 256, SM_TOTAL>>>(
            src, p_n, wl, b0, b1, p_deg, dst, Nn);
        src = dst;
    }

    // ---- z = y1 + ylast; zagg; final 128->3 --------------------------------
    add_z<<<q_blocks, 256>>>(p_y1, aux, p_ya, nquads);
    agg<<<agg_blocks, 256>>>(p_rs, p_deg, p_adj, p_ya, p_n, Nn);
    final3<<<node_blocks, 256>>>(p_ya, p_n, W0_l, b0_l, W1_l, b1_l,
                                 p_deg, vert, Nn);
}

// round 11
// speedup vs baseline: 1.0670x; 1.0670x over previous
#include <cuda_runtime.h>
#include <cuda_bf16.h>
#include <cstdint>

// ---------------------------------------------------------------------------
// GraphConv stack, R11: R8 linearity algebra + R7 tile geometry.
//   agg(X@W1^T + b1) = (agg X)@W1^T + deg*b1
// Per layer: Xagg = gather-sum(X) ; Y = relu(X@W0^T + Xagg@W1^T + b0 + deg*b1)
// Fused single-output HMMA GEMM, 64-row tiles, single A buffer (64KB) with
// register prefetch of the next tile's fp32 (LDG hidden under MMA).
// ---------------------------------------------------------------------------

#define D 128
#define MAXN 100352
#define MAXE 310016
#define MAXL 16

typedef unsigned int uint32;

// Scratch (device globals: no allocation allowed)
__device__ __align__(128) float g_y1[(size_t)MAXN * D];
__device__ __align__(128) float g_ya[(size_t)MAXN * D];
__device__ __align__(128) float g_yb[(size_t)MAXN * D];
__device__ __align__(128) float g_n [(size_t)MAXN * D];
__device__ __align__(128) __nv_bfloat16 g_wimg[(size_t)MAXL * 4 * D * D];
// CSR scratch
__device__ int g_deg[MAXN];
__device__ int g_rowstart[MAXN];
__device__ int g_wr[MAXN];
__device__ int g_adj[2 * MAXE];
__device__ int g_cursor;

// ---------------- helpers ---------------------------------------------------
__device__ __forceinline__ uint32 smem_to_u32(const void* p) {
    uint32 a;
    asm("{ .reg .u64 t; cvta.to.shared.u64 t, %1; cvt.u32.u64 %0, t; }"
        : "=r"(a) : "l"(p));
    return a;
}
__device__ __forceinline__ void ldm_x4(uint32 a, uint32* r) {
    asm volatile("ldmatrix.sync.aligned.m8n8.x4.shared.b16 {%0,%1,%2,%3}, [%4];"
                 : "=r"(r[0]), "=r"(r[1]), "=r"(r[2]), "=r"(r[3]) : "r"(a));
}
__device__ __forceinline__ void mma_bf16(float* d, const uint32* a, const uint32* b) {
    asm volatile(
        "mma.sync.aligned.m16n8k16.row.col.f32.bf16.bf16.f32 "
        "{%0,%1,%2,%3}, {%4,%5,%6,%7}, {%8,%9}, {%0,%1,%2,%3};"
        : "+f"(d[0]), "+f"(d[1]), "+f"(d[2]), "+f"(d[3])
        : "r"(a[0]), "r"(a[1]), "r"(a[2]), "r"(a[3]), "r"(b[0]), "r"(b[1]));
}
#define CP_ASYNC16(dst, src) \
    asm volatile("cp.async.cg.shared.global [%0], [%1], 16;" \
                 :: "r"(dst), "l"(src) : "memory")
#define CP_COMMIT() asm volatile("cp.async.commit_group;" ::: "memory")
#define CP_WAIT0()  asm volatile("cp.async.wait_group 0;" ::: "memory")

// Swizzled layout for a [rows x 128] bf16 k-major tile:
// row r, 16B chunk c (0..15): off = r*256 + ((c ^ (r&7)) << 4)
__host__ __device__ __forceinline__ uint32 tile_off(int r, int c) {
    return (uint32)(r * 256 + (((c) ^ (r & 7)) << 4));
}

// SMEM: A single buffer 64 rows: Xhi 16K | Xlo 16K | Ghi 16K | Glo 16K = 64KB
//       B: {W0hi, W0lo, W1hi, W1lo} 4 x 32KB = 128KB at SM_B
#define A_XLO    16384
#define A_GHI    32768
#define A_GLO    49152
#define SM_B     65536
#define SM_TOTAL (65536 + 131072)   // 192 KB

// ---------------------------------------------------------------------------
// Weight prep: split fp32 W into bf16 hi/lo in the swizzled image layout.
// Image layout per layer: {W0hi, W0lo, W1hi, W1lo}, 32KB each.
// ---------------------------------------------------------------------------
__global__ __launch_bounds__(256) void convert_weights(
    const float* __restrict__ W0_1, const float* __restrict__ W1_1,
    const float* __restrict__ W0_h, const float* __restrict__ W1_h,
    __nv_bfloat16* __restrict__ wimg)
{
    int m = blockIdx.x;
    int layer = m >> 1, sel = m & 1;
    const float* src;
    if (layer == 0) src = sel ? W1_1 : W0_1;
    else            src = (sel ? W1_h : W0_h) + (size_t)(layer - 1) * D * D;
    char* hi = (char*)(wimg + ((size_t)layer * 4 + sel * 2) * (D * D));
    char* lo = hi + D * D * 2;

    for (int e = threadIdx.x; e < 2048; e += blockDim.x) {   // 16B chunks
        int r = e >> 4, c = e & 15;
        const float* s = src + r * D + c * 8;
        uint32 h[4], l[4];
#pragma unroll
        for (int q = 0; q < 4; q++) {
            float x0 = s[q * 2], x1 = s[q * 2 + 1];
            __nv_bfloat16 h0 = __float2bfloat16(x0), h1 = __float2bfloat16(x1);
            __nv_bfloat16 l0 = __float2bfloat16(x0 - __bfloat162float(h0));
            __nv_bfloat16 l1 = __float2bfloat16(x1 - __bfloat162float(h1));
            __nv_bfloat162 hp = __halves2bfloat162(h0, h1);
            __nv_bfloat162 lp = __halves2bfloat162(l0, l1);
            h[q] = *(uint32*)&hp;
            l[q] = *(uint32*)&lp;
        }
        uint32 off = tile_off(r, c);
        *(uint4*)(hi + off) = make_uint4(h[0], h[1], h[2], h[3]);
        *(uint4*)(lo + off) = make_uint4(l[0], l[1], l[2], l[3]);
    }
}

// ---- A tile: 64 rows x 32 float4 x 2 sources = 4096 chunks / 256 thr = 16 --
__device__ __forceinline__ void ldA(const float* __restrict__ X,
                                    const float* __restrict__ G, int row0,
                                    int nrows, int tid, float4* pf) {
#pragma unroll
    for (int q = 0; q < 16; q++) {
        int idx = tid + (q & 7) * 256;       // 0..2047
        int r = idx >> 5, cq = idx & 31;
        int gr = row0 + r;
        const float* src = (q < 8) ? X : G;
        float4 v = make_float4(0.f, 0.f, 0.f, 0.f);
        if (gr < nrows) v = __ldg((const float4*)(src + (size_t)gr * D + cq * 4));
        pf[q] = v;
    }
}
__device__ __forceinline__ void cvt1(float x, float y, uint32& h, uint32& l) {
    __nv_bfloat16 hx = __float2bfloat16(x), hy = __float2bfloat16(y);
    __nv_bfloat16 lx = __float2bfloat16(x - __bfloat162float(hx));
    __nv_bfloat16 ly = __float2bfloat16(y - __bfloat162float(hy));
    __nv_bfloat162 hp = __halves2bfloat162(hx, hy);
    __nv_bfloat162 lp = __halves2bfloat162(lx, ly);
    h = *(uint32*)&hp; l = *(uint32*)&lp;
}
__device__ __forceinline__ void cvtA(char* smem, int tid, const float4* pf) {
#pragma unroll
    for (int q = 0; q < 16; q++) {
        int idx = tid + (q & 7) * 256;
        int r = idx >> 5, cq = idx & 31;
        uint32 hiOff = (q < 8) ? 0u : (uint32)A_GHI;
        float4 v = pf[q];
        uint32 h0, l0, h1, l1;
        cvt1(v.x, v.y, h0, l0);
        cvt1(v.z, v.w, h1, l1);
        uint32 off = tile_off(r, cq >> 1) + (cq & 1) * 8;
        *(uint2*)(smem + hiOff + off)         = make_uint2(h0, h1);
        *(uint2*)(smem + hiOff + 16384 + off) = make_uint2(l0, l1);
    }
}

// ---------------------------------------------------------------------------
// Persistent fused HMMA GEMM: Y = relu(X@W0^T + G@W1^T + b0 + deg*b1)
// grid = min(#SM, ntiles). 256 threads = 8 warps (2M x 4N), tile 64 x 128,
// warp tile 32 x 32. Single A buffer; next tile prefetched into registers.
// ---------------------------------------------------------------------------
__global__ __launch_bounds__(256) void gemm_fused(
    const float* __restrict__ X, const float* __restrict__ G,
    const __nv_bfloat16* __restrict__ wimg,
    const float* __restrict__ b0, const float* __restrict__ b1,
    const int* __restrict__ deg,
    float* __restrict__ Y, int nrows)
{
    extern __shared__ char smem[];
    const uint32 sb = smem_to_u32(smem);
    const int tid  = threadIdx.x;
    const int wid  = tid >> 5;
    const int lane = tid & 31;
    const int ntiles = (nrows + 63) >> 6;

    // ---- B: one 128KB cp.async of the pre-swizzled weight image -----------
    {
        const char* src = (const char*)wimg;
#pragma unroll
        for (int i = 0; i < 32; i++) {
            uint32 off = (uint32)(tid + i * 256) * 16;
            CP_ASYNC16(sb + SM_B + off, src + off);
        }
        CP_COMMIT();
    }

    // ---- prologue: load + convert first tile -------------------------------
    if (blockIdx.x < ntiles) {
        float4 pf[16];
        ldA(X, G, blockIdx.x * 64, nrows, tid, pf);
        cvtA(smem, tid, pf);
    }
    CP_WAIT0();
    __syncthreads();

    // ---- fragment addressing ------------------------------------------------
    const int warpM = wid >> 2;          // 0..1 -> rows warpM*32
    const int warpN = wid & 3;           // 0..3 -> cols warpN*32
    const int g  = lane >> 3;
    const int r8 = lane & 7;

    const int rowA = warpM * 32 + ((g & 1) << 3) + r8;
    const int swzA = rowA & 7;
    uint32 aRel[2];
#pragma unroll
    for (int i = 0; i < 2; i++) aRel[i] = (uint32)(rowA + i * 16) * 256;

    const int rowB = warpN * 32 + ((g >> 1) << 3) + r8;
    const int swzB = rowB & 7;
    uint32 bBase[2];
#pragma unroll
    for (int jj = 0; jj < 2; jj++)
        bBase[jj] = sb + SM_B + (uint32)(rowB + jj * 16) * 256;

    // bias registers
    float b0x[4], b0y[4], b1x[4], b1y[4];
#pragma unroll
    for (int j = 0; j < 4; j++) {
        int nc = warpN * 32 + j * 8 + (lane & 3) * 2;
        b0x[j] = __ldg(b0 + nc); b0y[j] = __ldg(b0 + nc + 1);
        b1x[j] = __ldg(b1 + nc); b1y[j] = __ldg(b1 + nc + 1);
    }

    // ---- main loop: register-prefetch pipeline ------------------------------
    for (int t = blockIdx.x; t < ntiles; t += gridDim.x) {
        const int tn = t + gridDim.x;
        const bool have = tn < ntiles;
        float4 pf[16];
        if (have) ldA(X, G, tn * 64, nrows, tid, pf);   // LDG overlaps MMA

        const int row0 = t * 64;

        float acc[2][4][4];
#pragma unroll
        for (int i = 0; i < 2; i++)
#pragma unroll
            for (int j = 0; j < 4; j++)
#pragma unroll
                for (int q = 0; q < 4; q++) acc[i][j][q] = 0.f;

#pragma unroll
        for (int k = 0; k < 8; k++) {
            const uint32 offA = (uint32)(((2 * k + (g >> 1)) ^ swzA) << 4);
            const uint32 offB = (uint32)(((2 * k + (g & 1)) ^ swzB) << 4);

            uint32 xh[2][4], xl[2][4], gh[2][4], gl[2][4];
#pragma unroll
            for (int i = 0; i < 2; i++) {
                ldm_x4(sb + aRel[i] + offA,          xh[i]);
                ldm_x4(sb + aRel[i] + offA + A_XLO,  xl[i]);
                ldm_x4(sb + aRel[i] + offA + A_GHI,  gh[i]);
                ldm_x4(sb + aRel[i] + offA + A_GLO,  gl[i]);
            }
            uint32 w0h[2][4], w0l[2][4], w1h[2][4], w1l[2][4];
#pragma unroll
            for (int jj = 0; jj < 2; jj++) {
                ldm_x4(bBase[jj] + offB,          w0h[jj]);
                ldm_x4(bBase[jj] + offB + 32768,  w0l[jj]);
                ldm_x4(bBase[jj] + offB + 65536,  w1h[jj]);
                ldm_x4(bBase[jj] + offB + 98304,  w1l[jj]);
            }
#pragma unroll
            for (int i = 0; i < 2; i++) {
#pragma unroll
                for (int j = 0; j < 4; j++) {
                    float* a = acc[i][j];
                    const int jj = j >> 1, js = (j & 1) * 2;
                    mma_bf16(a, xh[i], &w0h[jj][js]);   // Xhi*W0hi
                    mma_bf16(a, xh[i], &w0l[jj][js]);   // Xhi*W0lo
                    mma_bf16(a, xl[i], &w0h[jj][js]);   // Xlo*W0hi
                    mma_bf16(a, gh[i], &w1h[jj][js]);   // Ghi*W1hi
                    mma_bf16(a, gh[i], &w1l[jj][js]);   // Ghi*W1lo
                    mma_bf16(a, gl[i], &w1h[jj][js]);   // Glo*W1hi
                }
            }
        }

        // epilogue: + b0 + deg*b1, relu, store
#pragma unroll
        for (int i = 0; i < 2; i++) {
            int r1 = row0 + warpM * 32 + i * 16 + (lane >> 2);
            int r2 = r1 + 8;
            float d1 = (r1 < nrows) ? (float)__ldg(&deg[r1]) : 0.f;
            float d2 = (r2 < nrows) ? (float)__ldg(&deg[r2]) : 0.f;
#pragma unroll
            for (int j = 0; j < 4; j++) {
                int nc = warpN * 32 + j * 8 + (lane & 3) * 2;
                if (r1 < nrows) {
                    float vx = fmaxf(acc[i][j][0] + b0x[j] + d1 * b1x[j], 0.f);
                    float vy = fmaxf(acc[i][j][1] + b0y[j] + d1 * b1y[j], 0.f);
                    *(float2*)(Y + (size_t)r1 * D + nc) = make_float2(vx, vy);
                }
                if (r2 < nrows) {
                    float vx = fmaxf(acc[i][j][2] + b0x[j] + d2 * b1x[j], 0.f);
                    float vy = fmaxf(acc[i][j][3] + b0y[j] + d2 * b1y[j], 0.f);
                    *(float2*)(Y + (size_t)r2 * D + nc) = make_float2(vx, vy);
                }
            }
        }

        __syncthreads();                 // all warps done reading A buffer
        if (have) cvtA(smem, tid, pf);   // write next tile (CVT+STS only)
        __syncthreads();                 // buffer ready for next iteration
    }
}

// ---------------------------------------------------------------------------
// CSR build (once per call).
// ---------------------------------------------------------------------------
__global__ __launch_bounds__(256) void csr_zero(int* deg, int* cursor, int Nn) {
    int i = blockIdx.x * blockDim.x + threadIdx.x;
    if (i < Nn) deg[i] = 0;
    if (i == 0) *cursor = 0;
}
__global__ __launch_bounds__(256) void csr_count(const int2* __restrict__ edges,
                                                 int* deg, int E) {
    int e = blockIdx.x * blockDim.x + threadIdx.x;
    if (e >= E) return;
    int2 ij = __ldg(&edges[e]);
    atomicAdd(&deg[ij.x], 1);
    atomicAdd(&deg[ij.y], 1);
}
__global__ __launch_bounds__(256) void csr_offsets(const int* __restrict__ deg,
                                                   int* rowstart, int* wr,
                                                   int* cursor, int Nn) {
    int i = blockIdx.x * blockDim.x + threadIdx.x;
    if (i >= Nn) return;
    int s = atomicAdd(cursor, deg[i]);
    rowstart[i] = s;
    wr[i] = s;
}
__global__ __launch_bounds__(256) void csr_fill(const int2* __restrict__ edges,
                                                int* wr, int* adj, int E) {
    int e = blockIdx.x * blockDim.x + threadIdx.x;
    if (e >= E) return;
    int2 ij = __ldg(&edges[e]);
    adj[atomicAdd(&wr[ij.x], 1)] = ij.y;
    adj[atomicAdd(&wr[ij.y], 1)] = ij.x;
}

// ---------------------------------------------------------------------------
// Aggregation: one warp per node. Xagg[node] = sum_{nbr} X[nbr]. Fresh write.
// ---------------------------------------------------------------------------
__global__ __launch_bounds__(256) void agg(
    const int* __restrict__ rowstart, const int* __restrict__ deg,
    const int* __restrict__ adj, const float* __restrict__ X,
    float* __restrict__ Xagg, int Nn)
{
    int gidx = blockIdx.x * blockDim.x + threadIdx.x;
    int node = gidx >> 5;
    int lane = gidx & 31;
    if (node >= Nn) return;
    int d = __ldg(&deg[node]);
    int base = __ldg(&rowstart[node]);

    float4 acc = make_float4(0.f, 0.f, 0.f, 0.f);
    int t = 0;
    for (; t + 2 <= d; t += 2) {
        int n0 = __ldg(&adj[base + t]);
        int n1 = __ldg(&adj[base + t + 1]);
        float4 v0 = __ldg((const float4*)(X + (size_t)n0 * D + lane * 4));
        float4 v1 = __ldg((const float4*)(X + (size_t)n1 * D + lane * 4));
        acc.x += v0.x + v1.x; acc.y += v0.y + v1.y;
        acc.z += v0.z + v1.z; acc.w += v0.w + v1.w;
    }
    if (t < d) {
        int n0 = __ldg(&adj[base + t]);
        float4 v0 = __ldg((const float4*)(X + (size_t)n0 * D + lane * 4));
        acc.x += v0.x; acc.y += v0.y; acc.z += v0.z; acc.w += v0.w;
    }
    *(float4*)(Xagg + (size_t)node * D + lane * 4) = acc;
}

// ---------------------------------------------------------------------------
// z = y1 + ylast (both already relu'd)
// ---------------------------------------------------------------------------
__global__ __launch_bounds__(256) void add_z(
    const float* __restrict__ y1, const float* __restrict__ yl,
    float* __restrict__ z, int nquads)
{
    int idx = blockIdx.x * blockDim.x + threadIdx.x;
    if (idx >= nquads) return;
    float4 a = ((const float4*)y1)[idx];
    float4 b = ((const float4*)yl)[idx];
    a.x += b.x; a.y += b.y; a.z += b.z; a.w += b.w;
    ((float4*)z)[idx] = a;
}

// ---------------------------------------------------------------------------
// Final layer (128 -> 3): vert = z@W0^T + b0 + zagg@W1^T + deg*b1.
// ---------------------------------------------------------------------------
__global__ __launch_bounds__(256) void final3(
    const float* __restrict__ z, const float* __restrict__ zagg,
    const float* __restrict__ W0, const float* __restrict__ b0,
    const float* __restrict__ W1, const float* __restrict__ b1,
    const int* __restrict__ deg,
    float* __restrict__ vert, int nrows)
{
    __shared__ float sW0[3 * D], sW1[3 * D], sb0[3], sb1[3];
    for (int t = threadIdx.x; t < 3 * D; t += blockDim.x) {
        sW0[t] = W0[t];
        sW1[t] = W1[t];
    }
    if (threadIdx.x < 3) {
        sb0[threadIdx.x] = b0[threadIdx.x];
        sb1[threadIdx.x] = b1[threadIdx.x];
    }
    __syncthreads();

    int node = blockIdx.x * blockDim.x + threadIdx.x;
    if (node >= nrows) return;

    const float4* z4 = (const float4*)(z    + (size_t)node * D);
    const float4* a4 = (const float4*)(zagg + (size_t)node * D);
    float dg = (float)__ldg(&deg[node]);

    float acc[3];
#pragma unroll
    for (int o = 0; o < 3; o++) acc[o] = sb0[o] + dg * sb1[o];

#pragma unroll 8
    for (int q = 0; q < D / 4; q++) {
        float4 zv = z4[q], av = a4[q];
        int k = q * 4;
#pragma unroll
        for (int o = 0; o < 3; o++) {
            acc[o] = fmaf(zv.x, sW0[o * D + k + 0], acc[o]);
            acc[o] = fmaf(zv.y, sW0[o * D + k + 1], acc[o]);
            acc[o] = fmaf(zv.z, sW0[o * D + k + 2], acc[o]);
            acc[o] = fmaf(zv.w, sW0[o * D + k + 3], acc[o]);
            acc[o] = fmaf(av.x, sW1[o * D + k + 0], acc[o]);
            acc[o] = fmaf(av.y, sW1[o * D + k + 1], acc[o]);
            acc[o] = fmaf(av.z, sW1[o * D + k + 2], acc[o]);
            acc[o] = fmaf(av.w, sW1[o * D + k + 3], acc[o]);
        }
    }
#pragma unroll
    for (int o = 0; o < 3; o++)
        vert[(size_t)node * 3 + o] = acc[o];
}

// ---------------------------------------------------------------------------
extern "C" void kernel_launch(void* const* d_in, const int* in_sizes, int n_in,
                              void* d_out, int out_size)
{
    const float* features = (const float*)d_in[0];
    const int2*  edges    = (const int2*) d_in[1];
    const float* W0_1 = (const float*)d_in[2];
    const float* b0_1 = (const float*)d_in[3];
    const float* W1_1 = (const float*)d_in[4];
    const float* b1_1 = (const float*)d_in[5];
    const float* W0_h = (const float*)d_in[6];
    const float* b0_h = (const float*)d_in[7];
    const float* W1_h = (const float*)d_in[8];
    const float* b1_h = (const float*)d_in[9];
    const float* W0_l = (const float*)d_in[10];
    const float* b0_l = (const float*)d_in[11];
    const float* W1_l = (const float*)d_in[12];
    const float* b1_l = (const float*)d_in[13];

    const int Nn = in_sizes[0] / D;
    const int E  = in_sizes[1] / 2;
    const int Lh = in_sizes[6] / (D * D);

    float* out  = (float*)d_out;
    float* vert = out;                       // [N, 3]
    float* aux  = out + (size_t)Nn * 3;      // [N, 128] = relu'd last hidden

    float *p_y1, *p_ya, *p_yb, *p_n;
    __nv_bfloat16* p_wimg;
    int *p_deg, *p_rs, *p_wr, *p_adj, *p_cur;
    cudaGetSymbolAddress((void**)&p_y1,   g_y1);
    cudaGetSymbolAddress((void**)&p_ya,   g_ya);
    cudaGetSymbolAddress((void**)&p_yb,   g_yb);
    cudaGetSymbolAddress((void**)&p_n,    g_n);
    cudaGetSymbolAddress((void**)&p_wimg, g_wimg);
    cudaGetSymbolAddress((void**)&p_deg,  g_deg);
    cudaGetSymbolAddress((void**)&p_rs,   g_rowstart);
    cudaGetSymbolAddress((void**)&p_wr,   g_wr);
    cudaGetSymbolAddress((void**)&p_adj,  g_adj);
    cudaGetSymbolAddress((void**)&p_cur,  g_cursor);

    cudaFuncSetAttribute(gemm_fused, cudaFuncAttributeMaxDynamicSharedMemorySize, SM_TOTAL);

    int smc = 0;
    if (cudaDeviceGetAttribute(&smc, cudaDevAttrMultiProcessorCount, 0) != cudaSuccess
        || smc <= 0)
        smc = 148;

    const int ntiles      = (Nn + 63) / 64;
    const int gemm_grid   = smc < ntiles ? smc : ntiles;
    const int nquads      = Nn * D / 4;
    const int q_blocks    = (nquads + 255) / 256;
    const int node_blocks = (Nn + 255) / 256;
    const int edge_blocks = (E + 255) / 256;
    const int agg_blocks  = (Nn * 32 + 255) / 256;

    // ---- weight images + CSR build -----------------------------------------
    convert_weights<<<2 * (Lh + 1), 256>>>(W0_1, W1_1, W0_h, W1_h, p_wimg);
    csr_zero<<<node_blocks, 256>>>(p_deg, p_cur, Nn);
    csr_count<<<edge_blocks, 256>>>(edges, p_deg, E);
    csr_offsets<<<node_blocks, 256>>>(p_deg, p_rs, p_wr, p_cur, Nn);
    csr_fill<<<edge_blocks, 256>>>(edges, p_wr, p_adj, E);

    // ---- Layer 1: agg(features), fused GEMM -> relu'd y1 -------------------
    agg<<<agg_blocks, 256>>>(p_rs, p_deg, p_adj, features, p_n, Nn);
    gemm_fused<<<gemm_grid, 256, SM_TOTAL>>>(
        features, p_n, p_wimg, b0_1, b1_1, p_deg, p_y1, Nn);

    // ---- hidden layers (last one writes straight into aux) -----------------
    const float* src = p_y1;
    for (int l = 0; l < Lh; l++) {
        const __nv_bfloat16* wl = p_wimg + (size_t)(l + 1) * 4 * D * D;
        const float* b0 = b0_h + (size_t)l * D;
        const float* b1 = b1_h + (size_t)l * D;
        float* dst = (l == Lh - 1) ? aux : ((l & 1) ? p_yb : p_ya);
        agg<<<agg_blocks, 256>>>(p_rs, p_deg, p_adj, src, p_n, Nn);
        gemm_fused<<<gemm_grid, 256, SM_TOTAL>>>(
            src, p_n, wl, b0, b1, p_deg, dst, Nn);
        src = dst;
    }

    // ---- z = y1 + ylast; zagg; final 128->3 --------------------------------
    add_z<<<q_blocks, 256>>>(p_y1, aux, p_ya, nquads);
    agg<<<agg_blocks, 256>>>(p_rs, p_deg, p_adj, p_ya, p_n, Nn);
    final3<<<node_blocks, 256>>>(p_ya, p_n, W0_l, b0_l, W1_l, b1_l,
                                 p_deg, vert, Nn);
}